// round 1
// baseline (speedup 1.0000x reference)
#include <cuda_runtime.h>
#include <math.h>

// Problem constants
#define B_SZ 4
#define NSEQ 2048
#define DIM  1024
#define MX   (B_SZ * NSEQ)   // 8192 rows of x

// Scratch (device globals — no allocation allowed)
__device__ float g_q[(size_t)B_SZ * NSEQ * DIM];
__device__ float g_k[(size_t)B_SZ * NSEQ * DIM];
__device__ float g_v[(size_t)B_SZ * NSEQ * DIM];
__device__ float g_s[(size_t)B_SZ * NSEQ * NSEQ];

// ---------------------------------------------------------------------------
// Tiled SGEMM: C = scale * (A @ op(B)) [+ bias]
//   A: [M, K] row-major
//   BT=true : B is [N, K] row-major (NT gemm, C[m,n] = sum_k A[m,k]*B[n,k])
//   BT=false: B is [K, N] row-major (NN gemm)
//   Batched via blockIdx.z with element strides sA/sB/sC.
// All of M, N divisible by 128; K divisible by 8. No bounds checks.
// ---------------------------------------------------------------------------
#define BM 128
#define BN 128
#define BK 8
#define PAD 4

template <bool BT>
__global__ __launch_bounds__(256, 2)
void gemm_kernel(const float* __restrict__ A, const float* __restrict__ Bm,
                 const float* __restrict__ bias, float* __restrict__ C,
                 int M, int N, int K, float scale,
                 long long sA, long long sB, long long sC)
{
    __shared__ float As[BK][BM + PAD];
    __shared__ float Bs[BK][BN + PAD];

    const int tid = threadIdx.x;      // 256 threads
    const int bz  = blockIdx.z;
    A  += (size_t)bz * sA;
    Bm += (size_t)bz * sB;
    C  += (size_t)bz * sC;

    const int bm0 = blockIdx.y * BM;
    const int bn0 = blockIdx.x * BN;

    // ---- A load mapping: one float4 per thread per tile, stored transposed
    const int am = tid >> 1;          // 0..127 (row within tile)
    const int ak = (tid & 1) * 4;     // 0 or 4 (k within tile)
    const float* aptr = A + (size_t)(bm0 + am) * K + ak;

    // ---- B load mapping
    const float* bptr;
    int b_i0, b_i1;                    // meanings depend on BT
    if (BT) {
        b_i0 = tid >> 1;               // n within tile
        b_i1 = (tid & 1) * 4;          // k within tile
        bptr = Bm + (size_t)(bn0 + b_i0) * K + b_i1;
    } else {
        b_i0 = tid >> 5;               // k within tile (0..7)
        b_i1 = (tid & 31) * 4;         // n within tile (0..124)
        bptr = Bm + (size_t)b_i0 * N + bn0 + b_i1;
    }

    const int tx = tid & 15;           // 0..15 -> 8 cols each
    const int ty = tid >> 4;           // 0..15 -> 8 rows each

    float acc[8][8];
#pragma unroll
    for (int i = 0; i < 8; i++)
#pragma unroll
        for (int j = 0; j < 8; j++) acc[i][j] = 0.0f;

    for (int kt = 0; kt < K; kt += BK) {
        // global -> shared
        float4 a = *(const float4*)aptr;
        aptr += BK;
        As[ak + 0][am] = a.x;
        As[ak + 1][am] = a.y;
        As[ak + 2][am] = a.z;
        As[ak + 3][am] = a.w;

        if (BT) {
            float4 b = *(const float4*)bptr;
            bptr += BK;
            Bs[b_i1 + 0][b_i0] = b.x;
            Bs[b_i1 + 1][b_i0] = b.y;
            Bs[b_i1 + 2][b_i0] = b.z;
            Bs[b_i1 + 3][b_i0] = b.w;
        } else {
            float4 b = *(const float4*)bptr;
            bptr += (size_t)BK * N;
            *(float4*)&Bs[b_i0][b_i1] = b;
        }
        __syncthreads();

        // compute 8x8 micro-tile
#pragma unroll
        for (int k = 0; k < BK; k++) {
            float4 a0 = *(const float4*)&As[k][ty * 8];
            float4 a1 = *(const float4*)&As[k][ty * 8 + 4];
            float4 b0 = *(const float4*)&Bs[k][tx * 8];
            float4 b1 = *(const float4*)&Bs[k][tx * 8 + 4];
            float ar[8] = {a0.x, a0.y, a0.z, a0.w, a1.x, a1.y, a1.z, a1.w};
            float br[8] = {b0.x, b0.y, b0.z, b0.w, b1.x, b1.y, b1.z, b1.w};
#pragma unroll
            for (int i = 0; i < 8; i++)
#pragma unroll
                for (int j = 0; j < 8; j++)
                    acc[i][j] = fmaf(ar[i], br[j], acc[i][j]);
        }
        __syncthreads();
    }

    // epilogue
    float bfrag[8];
#pragma unroll
    for (int j = 0; j < 8; j++)
        bfrag[j] = bias ? bias[bn0 + tx * 8 + j] : 0.0f;

#pragma unroll
    for (int i = 0; i < 8; i++) {
        const int row = bm0 + ty * 8 + i;
        float* crow = C + (size_t)row * N + bn0 + tx * 8;
        float4 o0, o1;
        o0.x = acc[i][0] * scale + bfrag[0];
        o0.y = acc[i][1] * scale + bfrag[1];
        o0.z = acc[i][2] * scale + bfrag[2];
        o0.w = acc[i][3] * scale + bfrag[3];
        o1.x = acc[i][4] * scale + bfrag[4];
        o1.y = acc[i][5] * scale + bfrag[5];
        o1.z = acc[i][6] * scale + bfrag[6];
        o1.w = acc[i][7] * scale + bfrag[7];
        *(float4*)crow       = o0;
        *(float4*)(crow + 4) = o1;
    }
}

// ---------------------------------------------------------------------------
// Row softmax over N=2048 elements, one block per row, in place.
// ---------------------------------------------------------------------------
__global__ __launch_bounds__(256)
void softmax_kernel(float* __restrict__ S)
{
    const int n = NSEQ;
    float* row = S + (size_t)blockIdx.x * n;
    const int tid  = threadIdx.x;
    const int lane = tid & 31;
    const int wid  = tid >> 5;
    __shared__ float red[8];

    // pass 1: max
    float m = -INFINITY;
    for (int i = tid; i < n; i += 256) m = fmaxf(m, row[i]);
#pragma unroll
    for (int o = 16; o > 0; o >>= 1) m = fmaxf(m, __shfl_xor_sync(0xffffffffu, m, o));
    if (lane == 0) red[wid] = m;
    __syncthreads();
    m = red[0];
#pragma unroll
    for (int i = 1; i < 8; i++) m = fmaxf(m, red[i]);
    __syncthreads();   // everyone done reading red before reuse

    // pass 2: exp + sum
    float s = 0.0f;
    for (int i = tid; i < n; i += 256) {
        float e = __expf(row[i] - m);
        row[i] = e;
        s += e;
    }
#pragma unroll
    for (int o = 16; o > 0; o >>= 1) s += __shfl_xor_sync(0xffffffffu, s, o);
    if (lane == 0) red[wid] = s;
    __syncthreads();
    float tot = red[0];
#pragma unroll
    for (int i = 1; i < 8; i++) tot += red[i];
    const float inv = 1.0f / tot;

    // pass 3: normalize
    for (int i = tid; i < n; i += 256) row[i] *= inv;
}

// ---------------------------------------------------------------------------
// Launch
// ---------------------------------------------------------------------------
extern "C" void kernel_launch(void* const* d_in, const int* in_sizes, int n_in,
                              void* d_out, int out_size)
{
    const float* x  = (const float*)d_in[0];
    const float* Wq = (const float*)d_in[1];
    const float* bq = (const float*)d_in[2];
    const float* Wk = (const float*)d_in[3];
    const float* bk = (const float*)d_in[4];
    const float* Wv = (const float*)d_in[5];
    const float* bv = (const float*)d_in[6];
    float* out = (float*)d_out;

    float *q, *k, *v, *s;
    cudaGetSymbolAddress((void**)&q, g_q);
    cudaGetSymbolAddress((void**)&k, g_k);
    cudaGetSymbolAddress((void**)&v, g_v);
    cudaGetSymbolAddress((void**)&s, g_s);

    const float attn_scale = 1.0f / sqrtf((float)DIM);   // 1/32

    dim3 block(256);

    // 1) QKV projections: [8192,1024] = x[8192,1024] @ W^T[1024,1024] + b
    {
        dim3 grid(DIM / BN, MX / BM, 1);
        gemm_kernel<true><<<grid, block>>>(x, Wq, bq, q, MX, DIM, DIM, 1.0f, 0, 0, 0);
        gemm_kernel<true><<<grid, block>>>(x, Wk, bk, k, MX, DIM, DIM, 1.0f, 0, 0, 0);
        gemm_kernel<true><<<grid, block>>>(x, Wv, bv, v, MX, DIM, DIM, 1.0f, 0, 0, 0);
    }

    // 2) S = scale * Q @ K^T   (per-batch, NT)
    {
        dim3 grid(NSEQ / BN, NSEQ / BM, B_SZ);
        gemm_kernel<true><<<grid, block>>>(q, k, nullptr, s,
                                           NSEQ, NSEQ, DIM, attn_scale,
                                           (long long)NSEQ * DIM,
                                           (long long)NSEQ * DIM,
                                           (long long)NSEQ * NSEQ);
    }

    // 3) softmax rows
    softmax_kernel<<<B_SZ * NSEQ, 256>>>(s);

    // 4) out = P @ V   (per-batch, NN)
    {
        dim3 grid(DIM / BN, NSEQ / BM, B_SZ);
        gemm_kernel<false><<<grid, block>>>(s, v, nullptr, out,
                                            NSEQ, DIM, NSEQ, 1.0f,
                                            (long long)NSEQ * NSEQ,
                                            (long long)NSEQ * DIM,
                                            (long long)NSEQ * DIM);
    }
}

// round 2
// speedup vs baseline: 2.6540x; 2.6540x over previous
#include <cuda_runtime.h>
#include <math.h>
#include <stdint.h>

// Problem constants
#define B_SZ 4
#define NSEQ 2048
#define DIM  1024
#define MX   (B_SZ * NSEQ)

// Scratch (device globals — no allocation allowed)
__device__ float g_q[(size_t)B_SZ * NSEQ * DIM];
__device__ float g_k[(size_t)B_SZ * NSEQ * DIM];
__device__ float g_v[(size_t)B_SZ * NSEQ * DIM];
__device__ float g_s[(size_t)B_SZ * NSEQ * NSEQ];

// ---------------------------------------------------------------------------
// TF32 tensor-core GEMM: C = scale * (A @ op(B)) [+ bias]
//   A: [M,K] row-major.
//   BT=true : B is [N,K] row-major (NT)
//   BT=false: B is [K,N] row-major (NN)
// Tiles: CTA 128x128, BK=16, 8 warps (2x4), warp tile 64x32,
// mma.sync m16n8k8 tf32. M,N % 128 == 0, K % 16 == 0 (all hold here).
// ---------------------------------------------------------------------------
#define BM 128
#define BN 128
#define BK 16
#define ASTR 20     // padded stride for [row][k] tiles: (g*20+t) mod 32 is a permutation
#define BSTR 136    // padded stride for [k][n] tile (NN): (t*136+g) mod 32 -> t*8+g, permutation

__device__ __forceinline__ uint32_t f2tf32(float f) {
    uint32_t u;
    asm("cvt.rna.tf32.f32 %0, %1;" : "=r"(u) : "f"(f));
    return u;
}

__device__ __forceinline__ void mma_tf32(float* c, const uint32_t* a, const uint32_t* b) {
    asm volatile(
        "mma.sync.aligned.m16n8k8.row.col.f32.tf32.tf32.f32 "
        "{%0,%1,%2,%3}, {%4,%5,%6,%7}, {%8,%9}, {%0,%1,%2,%3};"
        : "+f"(c[0]), "+f"(c[1]), "+f"(c[2]), "+f"(c[3])
        : "r"(a[0]), "r"(a[1]), "r"(a[2]), "r"(a[3]),
          "r"(b[0]), "r"(b[1]));
}

template <bool BT>
__global__ __launch_bounds__(256, 2)
void gemm_tf32(const float* __restrict__ A, const float* __restrict__ Bm,
               const float* __restrict__ bias, float* __restrict__ C,
               int M, int N, int K, float scale,
               long long sA, long long sB, long long sC)
{
    __shared__ uint32_t As[BM * ASTR];                 // [m][k], stride 20
    __shared__ uint32_t Bs[BM * ASTR];                 // NT: [n][k] stride 20; NN: [k][n] stride 136 (fits)

    const int tid = threadIdx.x;
    const int bz  = blockIdx.z;
    A  += (size_t)bz * sA;
    Bm += (size_t)bz * sB;
    C  += (size_t)bz * sC;

    const int bm0 = blockIdx.y * BM;
    const int bn0 = blockIdx.x * BN;

    // ---- gmem loaders (register-staged prefetch) ----
    // A tile (and NT B tile): 128 rows x 16 cols = 512 float4; 2 per thread.
    const int lr = tid >> 2;            // 0..63  (row), second half at +64
    const int lc = (tid & 3) << 2;      // 0,4,8,12 (k)
    // NN B tile: 16 rows(k) x 128 cols = 512 float4; 2 per thread.
    const int nk = tid >> 5;            // 0..7 (k row), second at +8
    const int nc = (tid & 31) << 2;     // n col (0..124)

    float4 ra[2], rb[2];

    auto loadA = [&](int kt) {
#pragma unroll
        for (int r = 0; r < 2; r++)
            ra[r] = *(const float4*)(A + (size_t)(bm0 + lr + r * 64) * K + kt + lc);
    };
    auto loadB = [&](int kt) {
        if (BT) {
#pragma unroll
            for (int r = 0; r < 2; r++)
                rb[r] = *(const float4*)(Bm + (size_t)(bn0 + lr + r * 64) * K + kt + lc);
        } else {
#pragma unroll
            for (int r = 0; r < 2; r++)
                rb[r] = *(const float4*)(Bm + (size_t)(nk + r * 8) * N + bn0 + nc);
        }
    };
    auto loadB_at = [&](int kt) {
        if (BT) loadB(kt);
        else {
#pragma unroll
            for (int r = 0; r < 2; r++)
                rb[r] = *(const float4*)(Bm + (size_t)(kt + nk + r * 8) * N + bn0 + nc);
        }
    };
    auto stsA = [&]() {
#pragma unroll
        for (int r = 0; r < 2; r++) {
            uint32_t* p = &As[(lr + r * 64) * ASTR + lc];
            p[0] = f2tf32(ra[r].x); p[1] = f2tf32(ra[r].y);
            p[2] = f2tf32(ra[r].z); p[3] = f2tf32(ra[r].w);
        }
    };
    auto stsB = [&]() {
        if (BT) {
#pragma unroll
            for (int r = 0; r < 2; r++) {
                uint32_t* p = &Bs[(lr + r * 64) * ASTR + lc];
                p[0] = f2tf32(rb[r].x); p[1] = f2tf32(rb[r].y);
                p[2] = f2tf32(rb[r].z); p[3] = f2tf32(rb[r].w);
            }
        } else {
#pragma unroll
            for (int r = 0; r < 2; r++) {
                uint32_t* p = &Bs[(nk + r * 8) * BSTR + nc];
                p[0] = f2tf32(rb[r].x); p[1] = f2tf32(rb[r].y);
                p[2] = f2tf32(rb[r].z); p[3] = f2tf32(rb[r].w);
            }
        }
    };

    // ---- warp/fragment mapping ----
    const int wid  = tid >> 5;
    const int lane = tid & 31;
    const int g = lane >> 2;            // 0..7
    const int t = lane & 3;             // 0..3
    const int wm = (wid >> 2) * 64;     // warp row origin: 0 / 64
    const int wn = (wid & 3) * 32;      // warp col origin: 0/32/64/96

    float acc[4][4][4];
#pragma unroll
    for (int mi = 0; mi < 4; mi++)
#pragma unroll
        for (int ni = 0; ni < 4; ni++)
#pragma unroll
            for (int r = 0; r < 4; r++) acc[mi][ni][r] = 0.0f;

    loadA(0);
    loadB_at(0);

    for (int kt = 0; kt < K; kt += BK) {
        stsA();
        stsB();
        __syncthreads();

        if (kt + BK < K) {
            loadA(kt + BK);
            loadB_at(kt + BK);
        }

#pragma unroll
        for (int ks = 0; ks < 2; ks++) {
            const int k0 = ks * 8;
            uint32_t af[4][4];
#pragma unroll
            for (int mi = 0; mi < 4; mi++) {
                const int r0 = wm + mi * 16 + g;
                af[mi][0] = As[r0 * ASTR + k0 + t];
                af[mi][1] = As[(r0 + 8) * ASTR + k0 + t];
                af[mi][2] = As[r0 * ASTR + k0 + t + 4];
                af[mi][3] = As[(r0 + 8) * ASTR + k0 + t + 4];
            }
            uint32_t bf[4][2];
#pragma unroll
            for (int ni = 0; ni < 4; ni++) {
                const int n0 = wn + ni * 8 + g;
                if (BT) {
                    bf[ni][0] = Bs[n0 * ASTR + k0 + t];
                    bf[ni][1] = Bs[n0 * ASTR + k0 + t + 4];
                } else {
                    bf[ni][0] = Bs[(k0 + t) * BSTR + n0];
                    bf[ni][1] = Bs[(k0 + t + 4) * BSTR + n0];
                }
            }
#pragma unroll
            for (int mi = 0; mi < 4; mi++)
#pragma unroll
                for (int ni = 0; ni < 4; ni++)
                    mma_tf32(acc[mi][ni], af[mi], bf[ni]);
        }
        __syncthreads();
    }

    // ---- epilogue: scale, bias, float2 stores ----
    float bfr[4][2];
#pragma unroll
    for (int ni = 0; ni < 4; ni++) {
        const int col = bn0 + wn + ni * 8 + t * 2;
        bfr[ni][0] = bias ? bias[col] : 0.0f;
        bfr[ni][1] = bias ? bias[col + 1] : 0.0f;
    }
#pragma unroll
    for (int mi = 0; mi < 4; mi++) {
        const int row0 = bm0 + wm + mi * 16 + g;
#pragma unroll
        for (int ni = 0; ni < 4; ni++) {
            const int col = bn0 + wn + ni * 8 + t * 2;
            float2 v0, v1;
            v0.x = acc[mi][ni][0] * scale + bfr[ni][0];
            v0.y = acc[mi][ni][1] * scale + bfr[ni][1];
            v1.x = acc[mi][ni][2] * scale + bfr[ni][0];
            v1.y = acc[mi][ni][3] * scale + bfr[ni][1];
            *(float2*)(C + (size_t)row0 * N + col)       = v0;
            *(float2*)(C + (size_t)(row0 + 8) * N + col) = v1;
        }
    }
}

// ---------------------------------------------------------------------------
// Row softmax over N=2048 elements, one block per row, in place.
// ---------------------------------------------------------------------------
__global__ __launch_bounds__(256)
void softmax_kernel(float* __restrict__ S)
{
    const int n = NSEQ;
    float* row = S + (size_t)blockIdx.x * n;
    const int tid  = threadIdx.x;
    const int lane = tid & 31;
    const int wid  = tid >> 5;
    __shared__ float red[8];

    float m = -INFINITY;
    for (int i = tid; i < n; i += 256) m = fmaxf(m, row[i]);
#pragma unroll
    for (int o = 16; o > 0; o >>= 1) m = fmaxf(m, __shfl_xor_sync(0xffffffffu, m, o));
    if (lane == 0) red[wid] = m;
    __syncthreads();
    m = red[0];
#pragma unroll
    for (int i = 1; i < 8; i++) m = fmaxf(m, red[i]);
    __syncthreads();

    float s = 0.0f;
    for (int i = tid; i < n; i += 256) {
        float e = __expf(row[i] - m);
        row[i] = e;
        s += e;
    }
#pragma unroll
    for (int o = 16; o > 0; o >>= 1) s += __shfl_xor_sync(0xffffffffu, s, o);
    if (lane == 0) red[wid] = s;
    __syncthreads();
    float tot = red[0];
#pragma unroll
    for (int i = 1; i < 8; i++) tot += red[i];
    const float inv = 1.0f / tot;

    for (int i = tid; i < n; i += 256) row[i] *= inv;
}

// ---------------------------------------------------------------------------
// Launch
// ---------------------------------------------------------------------------
extern "C" void kernel_launch(void* const* d_in, const int* in_sizes, int n_in,
                              void* d_out, int out_size)
{
    const float* x  = (const float*)d_in[0];
    const float* Wq = (const float*)d_in[1];
    const float* bq = (const float*)d_in[2];
    const float* Wk = (const float*)d_in[3];
    const float* bk = (const float*)d_in[4];
    const float* Wv = (const float*)d_in[5];
    const float* bv = (const float*)d_in[6];
    float* out = (float*)d_out;

    float *q, *k, *v, *s;
    cudaGetSymbolAddress((void**)&q, g_q);
    cudaGetSymbolAddress((void**)&k, g_k);
    cudaGetSymbolAddress((void**)&v, g_v);
    cudaGetSymbolAddress((void**)&s, g_s);

    const float attn_scale = 1.0f / sqrtf((float)DIM);   // 1/32

    dim3 block(256);

    // 1) QKV projections: [8192,1024] = x @ W^T + b   (NT)
    {
        dim3 grid(DIM / BN, MX / BM, 1);
        gemm_tf32<true><<<grid, block>>>(x, Wq, bq, q, MX, DIM, DIM, 1.0f, 0, 0, 0);
        gemm_tf32<true><<<grid, block>>>(x, Wk, bk, k, MX, DIM, DIM, 1.0f, 0, 0, 0);
        gemm_tf32<true><<<grid, block>>>(x, Wv, bv, v, MX, DIM, DIM, 1.0f, 0, 0, 0);
    }

    // 2) S = scale * Q @ K^T   (per-batch, NT)
    {
        dim3 grid(NSEQ / BN, NSEQ / BM, B_SZ);
        gemm_tf32<true><<<grid, block>>>(q, k, nullptr, s,
                                         NSEQ, NSEQ, DIM, attn_scale,
                                         (long long)NSEQ * DIM,
                                         (long long)NSEQ * DIM,
                                         (long long)NSEQ * NSEQ);
    }

    // 3) softmax rows
    softmax_kernel<<<B_SZ * NSEQ, 256>>>(s);

    // 4) out = P @ V   (per-batch, NN)
    {
        dim3 grid(DIM / BN, NSEQ / BM, B_SZ);
        gemm_tf32<false><<<grid, block>>>(s, v, nullptr, out,
                                          NSEQ, DIM, NSEQ, 1.0f,
                                          (long long)NSEQ * NSEQ,
                                          (long long)NSEQ * DIM,
                                          (long long)NSEQ * DIM);
    }
}